// round 1
// baseline (speedup 1.0000x reference)
#include <cuda_runtime.h>
#include <math.h>

#define BB 2
#define SS 2048
#define EE 1024
#define HH 16
#define DD 64
#define N_QKV (3 * EE)

// Scratch (device globals — allocation-free)
__device__ float g_q[BB * HH * SS * DD];   // [b][h][s][d], pre-scaled by 1/sqrt(D)
__device__ float g_k[BB * HH * SS * DD];
__device__ float g_v[BB * HH * SS * DD];
__device__ float g_o[BB * SS * EE];        // [b][s][h*D+d] == (B*S, E) row-major

// ---------------------------------------------------------------------------
// Tiled SGEMM: C[M, N_COLS] = A[M, 1024] @ W[1024, N_COLS]
// BM=128, BN=128, BK=16, 256 threads, 8x8 microtile.
// QKV_SCATTER: epilogue scatters to g_q/g_k/g_v (Q scaled). Otherwise writes C.
// When !QKV_SCATTER, A is ignored and g_o is used as the A operand.
// ---------------------------------------------------------------------------
template <int N_COLS, bool QKV_SCATTER>
__global__ __launch_bounds__(256) void gemm128(const float* __restrict__ A,
                                               const float* __restrict__ W,
                                               float* __restrict__ C) {
    __shared__ float As[16][132];  // [k][m]
    __shared__ float Bs[16][132];  // [k][n]

    const int tid = threadIdx.x;
    const int tx = tid & 15;
    const int ty = tid >> 4;
    const int m0 = blockIdx.y * 128;
    const int n0 = blockIdx.x * 128;

    const float* __restrict__ Abase = QKV_SCATTER ? A : (const float*)g_o;

    float acc[8][8];
#pragma unroll
    for (int i = 0; i < 8; i++)
#pragma unroll
        for (int j = 0; j < 8; j++) acc[i][j] = 0.0f;

    for (int k0 = 0; k0 < EE; k0 += 16) {
        // Load A tile (128 x 16), store transposed As[k][m]
#pragma unroll
        for (int i = 0; i < 2; i++) {
            int idx = tid + i * 256;          // 0..511
            int r = idx >> 2;                 // 0..127
            int c4 = (idx & 3) * 4;           // 0,4,8,12
            float4 v = *(const float4*)(Abase + (size_t)(m0 + r) * EE + k0 + c4);
            As[c4 + 0][r] = v.x;
            As[c4 + 1][r] = v.y;
            As[c4 + 2][r] = v.z;
            As[c4 + 3][r] = v.w;
        }
        // Load W tile (16 x 128), natural layout
#pragma unroll
        for (int i = 0; i < 2; i++) {
            int idx = tid + i * 256;
            int r = idx >> 5;                 // 0..15
            int c4 = (idx & 31) * 4;          // 0..124
            *(float4*)&Bs[r][c4] =
                *(const float4*)(W + (size_t)(k0 + r) * N_COLS + n0 + c4);
        }
        __syncthreads();

#pragma unroll
        for (int k = 0; k < 16; k++) {
            float a[8], b[8];
            *(float4*)&a[0] = *(const float4*)&As[k][ty * 8];
            *(float4*)&a[4] = *(const float4*)&As[k][ty * 8 + 4];
            *(float4*)&b[0] = *(const float4*)&Bs[k][tx * 8];
            *(float4*)&b[4] = *(const float4*)&Bs[k][tx * 8 + 4];
#pragma unroll
            for (int ii = 0; ii < 8; ii++)
#pragma unroll
                for (int jj = 0; jj < 8; jj++) acc[ii][jj] += a[ii] * b[jj];
        }
        __syncthreads();
    }

    if (QKV_SCATTER) {
        // col f0..f0+7 all within one (c, h) block since f0 is 8-aligned
        int f0 = n0 + tx * 8;
        int c = f0 >> 10;                  // 0=Q, 1=K, 2=V
        int h = (f0 >> 6) & (HH - 1);
        int d0 = f0 & (DD - 1);
        float* dst = (c == 0) ? g_q : (c == 1) ? g_k : g_v;
        float sc = (c == 0) ? 0.125f : 1.0f;  // 1/sqrt(64)
#pragma unroll
        for (int ii = 0; ii < 8; ii++) {
            int row = m0 + ty * 8 + ii;
            int b = row >> 11;             // / SS
            int s = row & (SS - 1);
            float* p = dst + ((size_t)((b * HH + h) * SS + s)) * DD + d0;
            float4 v0 = make_float4(acc[ii][0] * sc, acc[ii][1] * sc,
                                    acc[ii][2] * sc, acc[ii][3] * sc);
            float4 v1 = make_float4(acc[ii][4] * sc, acc[ii][5] * sc,
                                    acc[ii][6] * sc, acc[ii][7] * sc);
            *(float4*)p = v0;
            *(float4*)(p + 4) = v1;
        }
    } else {
#pragma unroll
        for (int ii = 0; ii < 8; ii++) {
            int row = m0 + ty * 8 + ii;
            float* p = C + (size_t)row * N_COLS + n0 + tx * 8;
            *(float4*)p = make_float4(acc[ii][0], acc[ii][1], acc[ii][2], acc[ii][3]);
            *(float4*)(p + 4) = make_float4(acc[ii][4], acc[ii][5], acc[ii][6], acc[ii][7]);
        }
    }
}

// ---------------------------------------------------------------------------
// Flash attention: one CTA per (b, h, 64-row q tile). 256 threads (16x16),
// 4x4 microtile over the 64x64 score tile. Online softmax in registers.
// ---------------------------------------------------------------------------
__global__ __launch_bounds__(256) void attn_kernel() {
    extern __shared__ float sm[];
    float* Qs = sm;                  // [d][i], stride 68
    float* Ks = sm + 64 * 68;        // [d][j]
    float* Vs = sm + 2 * 64 * 68;    // [j][d]
    float* Ps = sm + 3 * 64 * 68;    // [i][j]

    const int tid = threadIdx.x;
    const int tx = tid & 15;
    const int ty = tid >> 4;
    const int q0 = blockIdx.x * 64;
    const int h = blockIdx.y;
    const int b = blockIdx.z;
    const size_t head_base = (size_t)(b * HH + h) * SS * DD;

    // Load Q tile transposed: Qs[d][i]
#pragma unroll
    for (int i = 0; i < 4; i++) {
        int idx = tid + i * 256;       // 0..1023
        int r = idx >> 4;              // 0..63
        int c4 = (idx & 15) * 4;       // 0..60
        float4 v = *(const float4*)(g_q + head_base + (size_t)(q0 + r) * DD + c4);
        Qs[(c4 + 0) * 68 + r] = v.x;
        Qs[(c4 + 1) * 68 + r] = v.y;
        Qs[(c4 + 2) * 68 + r] = v.z;
        Qs[(c4 + 3) * 68 + r] = v.w;
    }

    float accO[4][4];
    float mrow[4], lrow[4];
#pragma unroll
    for (int i = 0; i < 4; i++) {
        mrow[i] = -1.0e30f;
        lrow[i] = 0.0f;
#pragma unroll
        for (int j = 0; j < 4; j++) accO[i][j] = 0.0f;
    }

    for (int kv0 = 0; kv0 < SS; kv0 += 64) {
        __syncthreads();  // protect K/V/P (and Qs on iter 0) reuse
        // Load K transposed (Ks[d][j]) and V natural (Vs[j][d])
#pragma unroll
        for (int i = 0; i < 4; i++) {
            int idx = tid + i * 256;
            int r = idx >> 4;
            int c4 = (idx & 15) * 4;
            float4 kv = *(const float4*)(g_k + head_base + (size_t)(kv0 + r) * DD + c4);
            Ks[(c4 + 0) * 68 + r] = kv.x;
            Ks[(c4 + 1) * 68 + r] = kv.y;
            Ks[(c4 + 2) * 68 + r] = kv.z;
            Ks[(c4 + 3) * 68 + r] = kv.w;
            float4 vv = *(const float4*)(g_v + head_base + (size_t)(kv0 + r) * DD + c4);
            *(float4*)&Vs[r * 68 + c4] = vv;
        }
        __syncthreads();

        // S = (Q * scale) @ K^T   (scale already folded into Q)
        float s[4][4];
#pragma unroll
        for (int ii = 0; ii < 4; ii++)
#pragma unroll
            for (int jj = 0; jj < 4; jj++) s[ii][jj] = 0.0f;
#pragma unroll
        for (int d = 0; d < 64; d++) {
            float a[4], bb[4];
            *(float4*)a = *(const float4*)&Qs[d * 68 + ty * 4];
            *(float4*)bb = *(const float4*)&Ks[d * 68 + tx * 4];
#pragma unroll
            for (int ii = 0; ii < 4; ii++)
#pragma unroll
                for (int jj = 0; jj < 4; jj++) s[ii][jj] += a[ii] * bb[jj];
        }

        // Online softmax: reduce across the 16-thread tx group (lane bits 0..3)
#pragma unroll
        for (int ii = 0; ii < 4; ii++) {
            float mt = fmaxf(fmaxf(s[ii][0], s[ii][1]), fmaxf(s[ii][2], s[ii][3]));
#pragma unroll
            for (int off = 8; off >= 1; off >>= 1)
                mt = fmaxf(mt, __shfl_xor_sync(0xffffffffu, mt, off));
            float mnew = fmaxf(mrow[ii], mt);
            float fac = __expf(mrow[ii] - mnew);
            float p0 = __expf(s[ii][0] - mnew);
            float p1 = __expf(s[ii][1] - mnew);
            float p2 = __expf(s[ii][2] - mnew);
            float p3 = __expf(s[ii][3] - mnew);
            float rs = (p0 + p1) + (p2 + p3);
#pragma unroll
            for (int off = 8; off >= 1; off >>= 1)
                rs += __shfl_xor_sync(0xffffffffu, rs, off);
            lrow[ii] = lrow[ii] * fac + rs;
            mrow[ii] = mnew;
#pragma unroll
            for (int jj = 0; jj < 4; jj++) accO[ii][jj] *= fac;
            *(float4*)&Ps[(ty * 4 + ii) * 68 + tx * 4] = make_float4(p0, p1, p2, p3);
        }
        __syncthreads();

        // O += P @ V
#pragma unroll
        for (int j = 0; j < 64; j += 4) {
            float pp[4][4];
#pragma unroll
            for (int ii = 0; ii < 4; ii++)
                *(float4*)&pp[ii][0] = *(const float4*)&Ps[(ty * 4 + ii) * 68 + j];
#pragma unroll
            for (int q = 0; q < 4; q++) {
                float4 v4 = *(const float4*)&Vs[(j + q) * 68 + tx * 4];
#pragma unroll
                for (int ii = 0; ii < 4; ii++) {
                    accO[ii][0] += pp[ii][q] * v4.x;
                    accO[ii][1] += pp[ii][q] * v4.y;
                    accO[ii][2] += pp[ii][q] * v4.z;
                    accO[ii][3] += pp[ii][q] * v4.w;
                }
            }
        }
    }

    // Write O to g_o[(b*S+s)][h*D + d]  (== transpose(0,2,1,3).reshape)
#pragma unroll
    for (int ii = 0; ii < 4; ii++) {
        int srow = q0 + ty * 4 + ii;
        float inv = 1.0f / lrow[ii];
        float4 o = make_float4(accO[ii][0] * inv, accO[ii][1] * inv,
                               accO[ii][2] * inv, accO[ii][3] * inv);
        *(float4*)(g_o + ((size_t)(b * SS + srow)) * EE + h * DD + tx * 4) = o;
    }
}

// ---------------------------------------------------------------------------
extern "C" void kernel_launch(void* const* d_in, const int* in_sizes, int n_in,
                              void* d_out, int out_size) {
    const float* x = (const float*)d_in[0];      // (B, S, E)
    const float* w_qkv = (const float*)d_in[1];  // (E, 3E)
    const float* w_out = (const float*)d_in[2];  // (E, E)
    float* out = (float*)d_out;                  // (B, S, E)

    // 1) QKV projection + scatter into per-head Q/K/V (Q pre-scaled)
    gemm128<N_QKV, true>
        <<<dim3(N_QKV / 128, (BB * SS) / 128), 256>>>(x, w_qkv, nullptr);

    // 2) Flash attention
    const int smem_bytes = 4 * 64 * 68 * (int)sizeof(float);  // 69632
    cudaFuncSetAttribute(attn_kernel, cudaFuncAttributeMaxDynamicSharedMemorySize,
                         smem_bytes);
    attn_kernel<<<dim3(SS / 64, HH, BB), 256, smem_bytes>>>();

    // 3) Output projection
    gemm128<EE, false>
        <<<dim3(EE / 128, (BB * SS) / 128), 256>>>(nullptr, w_out, out);
}

// round 3
// speedup vs baseline: 1.6281x; 1.6281x over previous
#include <cuda_runtime.h>
#include <cuda_bf16.h>
#include <cstdint>
#include <math.h>

#define BB 2
#define SS 2048
#define EE 1024
#define HH 16
#define DD 64
#define NQKV 3072

// ---------------------------------------------------------------------------
// Scratch: bf16 hi/lo pairs (device globals — allocation-free).
// q is pre-scaled by 1/sqrt(D)=0.125 at QKV epilogue.
// ---------------------------------------------------------------------------
__device__ __nv_bfloat16 g_qh[BB*HH*SS*DD], g_ql[BB*HH*SS*DD];
__device__ __nv_bfloat16 g_kh[BB*HH*SS*DD], g_kl[BB*HH*SS*DD];
__device__ __nv_bfloat16 g_vh[BB*HH*SS*DD], g_vl[BB*HH*SS*DD];
__device__ __nv_bfloat16 g_oh[BB*SS*EE],    g_ol[BB*SS*EE];

// ---------------------------------------------------------------------------
// PTX wrappers
// ---------------------------------------------------------------------------
__device__ __forceinline__ void ldsm4(unsigned r[4], uint32_t a) {
    asm volatile("ldmatrix.sync.aligned.m8n8.x4.shared.b16 {%0,%1,%2,%3}, [%4];\n"
                 : "=r"(r[0]), "=r"(r[1]), "=r"(r[2]), "=r"(r[3]) : "r"(a));
}
__device__ __forceinline__ void ldsm4t(unsigned r[4], uint32_t a) {
    asm volatile("ldmatrix.sync.aligned.m8n8.x4.trans.shared.b16 {%0,%1,%2,%3}, [%4];\n"
                 : "=r"(r[0]), "=r"(r[1]), "=r"(r[2]), "=r"(r[3]) : "r"(a));
}
__device__ __forceinline__ void mma_bf16(float c[4], const unsigned a[4], const unsigned b[2]) {
    asm volatile(
        "mma.sync.aligned.m16n8k16.row.col.f32.bf16.bf16.f32 "
        "{%0,%1,%2,%3}, {%4,%5,%6,%7}, {%8,%9}, {%0,%1,%2,%3};\n"
        : "+f"(c[0]), "+f"(c[1]), "+f"(c[2]), "+f"(c[3])
        : "r"(a[0]), "r"(a[1]), "r"(a[2]), "r"(a[3]), "r"(b[0]), "r"(b[1]));
}
// split (x,y) fp32 pair into packed bf16x2 hi and lo (residual) words
__device__ __forceinline__ void split_pair(float x, float y, unsigned &hi, unsigned &lo) {
    __nv_bfloat162 h2 = __floats2bfloat162_rn(x, y);
    float xr = x - __bfloat162float(__low2bfloat16(h2));
    float yr = y - __bfloat162float(__high2bfloat16(h2));
    __nv_bfloat162 l2 = __floats2bfloat162_rn(xr, yr);
    hi = *reinterpret_cast<unsigned*>(&h2);
    lo = *reinterpret_cast<unsigned*>(&l2);
}

// ---------------------------------------------------------------------------
// bf16x3 GEMM: C[M, NC] = A[M,1024] @ W[1024,NC]
// BM=128, BN=128, BK=32, 8 warps, warp tile 32x64.
// A_BF16=false: A fp32 (x), epilogue scatters Q/K/V hi/lo (Q scaled).
// A_BF16=true:  A = g_oh/g_ol bf16 pairs, epilogue writes fp32 C.
// ---------------------------------------------------------------------------
template <int NC, bool A_BF16>
__global__ __launch_bounds__(256) void mma_gemm(const float* __restrict__ A,
                                                const float* __restrict__ W,
                                                float* __restrict__ C) {
    __shared__ __nv_bfloat16 Ah[128 * 40], Al[128 * 40];
    __shared__ __nv_bfloat16 Bh[32 * 136], Bl[32 * 136];

    const int tid = threadIdx.x;
    const int lane = tid & 31, wid = tid >> 5;
    const int wm = (wid & 3) * 32, wn = (wid >> 2) * 64;
    const int m0 = blockIdx.y * 128, n0 = blockIdx.x * 128;

    const uint32_t uAh = (uint32_t)__cvta_generic_to_shared(Ah);
    const uint32_t uAl = (uint32_t)__cvta_generic_to_shared(Al);
    const uint32_t uBh = (uint32_t)__cvta_generic_to_shared(Bh);
    const uint32_t uBl = (uint32_t)__cvta_generic_to_shared(Bl);

    const int lm_r = lane & 15, lm_c = (lane >> 4) * 8;  // A-frag & trans-B-frag lane map

    float acc[2][8][4];
#pragma unroll
    for (int i = 0; i < 2; i++)
#pragma unroll
        for (int j = 0; j < 8; j++)
#pragma unroll
            for (int q = 0; q < 4; q++) acc[i][j][q] = 0.0f;

    for (int k0 = 0; k0 < EE; k0 += 32) {
        __syncthreads();
        if (!A_BF16) {
            // A fp32 tile 128x32 -> split to bf16 hi/lo
#pragma unroll
            for (int i = 0; i < 4; i++) {
                int idx = tid + i * 256;          // 0..1023
                int r = idx >> 3, c4 = (idx & 7) * 4;
                float4 v = *(const float4*)(A + (size_t)(m0 + r) * EE + k0 + c4);
                unsigned h0, l0, h1, l1;
                split_pair(v.x, v.y, h0, l0);
                split_pair(v.z, v.w, h1, l1);
                *(uint2*)&Ah[r * 40 + c4] = make_uint2(h0, h1);
                *(uint2*)&Al[r * 40 + c4] = make_uint2(l0, l1);
            }
        } else {
            // A already split bf16 in g_oh/g_ol
#pragma unroll
            for (int i = 0; i < 2; i++) {
                int idx = tid + i * 256;          // 0..511
                int r = idx >> 2, c8 = (idx & 3) * 8;
                *(int4*)&Ah[r * 40 + c8] =
                    *(const int4*)(g_oh + (size_t)(m0 + r) * EE + k0 + c8);
                *(int4*)&Al[r * 40 + c8] =
                    *(const int4*)(g_ol + (size_t)(m0 + r) * EE + k0 + c8);
            }
        }
        // W fp32 tile 32x128 -> split
#pragma unroll
        for (int i = 0; i < 4; i++) {
            int idx = tid + i * 256;
            int r = idx >> 5, c4 = (idx & 31) * 4;
            float4 v = *(const float4*)(W + (size_t)(k0 + r) * NC + n0 + c4);
            unsigned h0, l0, h1, l1;
            split_pair(v.x, v.y, h0, l0);
            split_pair(v.z, v.w, h1, l1);
            *(uint2*)&Bh[r * 136 + c4] = make_uint2(h0, h1);
            *(uint2*)&Bl[r * 136 + c4] = make_uint2(l0, l1);
        }
        __syncthreads();

#pragma unroll
        for (int ks = 0; ks < 2; ks++) {
            const int kk = ks * 16;
            unsigned ah[2][4], al[2][4];
#pragma unroll
            for (int tm = 0; tm < 2; tm++) {
                uint32_t off = ((wm + tm * 16 + lm_r) * 40 + kk + lm_c) * 2;
                ldsm4(ah[tm], uAh + off);
                ldsm4(al[tm], uAl + off);
            }
            unsigned bh[4][4], bl[4][4];
#pragma unroll
            for (int g = 0; g < 4; g++) {
                uint32_t off = ((kk + lm_r) * 136 + wn + g * 16 + lm_c) * 2;
                ldsm4t(bh[g], uBh + off);
                ldsm4t(bl[g], uBl + off);
            }
#pragma unroll
            for (int tm = 0; tm < 2; tm++)
#pragma unroll
                for (int nt = 0; nt < 8; nt++) {
                    const unsigned* bhp = &bh[nt >> 1][(nt & 1) * 2];
                    const unsigned* blp = &bl[nt >> 1][(nt & 1) * 2];
                    mma_bf16(acc[tm][nt], ah[tm], bhp);
                    mma_bf16(acc[tm][nt], ah[tm], blp);
                    mma_bf16(acc[tm][nt], al[tm], bhp);
                }
        }
    }

    // Epilogue
    if (!A_BF16) {
        // scatter QKV -> g_{q,k,v}{h,l}  [b][h][s][d], Q scaled by 0.125
#pragma unroll
        for (int tm = 0; tm < 2; tm++)
#pragma unroll
            for (int nt = 0; nt < 8; nt++) {
                int f = n0 + wn + nt * 8 + (lane & 3) * 2;
                int cid = f >> 10;
                int hh = (f >> 6) & (HH - 1);
                int d = f & (DD - 1);
                float sc = (cid == 0) ? 0.125f : 1.0f;
                __nv_bfloat16* dh = (cid == 0) ? g_qh : (cid == 1) ? g_kh : g_vh;
                __nv_bfloat16* dl = (cid == 0) ? g_ql : (cid == 1) ? g_kl : g_vl;
#pragma unroll
                for (int half = 0; half < 2; half++) {
                    int row = m0 + wm + tm * 16 + (lane >> 2) + half * 8;
                    int b = row >> 11, s = row & (SS - 1);
                    size_t off = ((size_t)((b * HH + hh) * SS + s)) * DD + d;
                    unsigned hi, lo;
                    split_pair(acc[tm][nt][half * 2] * sc,
                               acc[tm][nt][half * 2 + 1] * sc, hi, lo);
                    *(unsigned*)&dh[off] = hi;
                    *(unsigned*)&dl[off] = lo;
                }
            }
    } else {
#pragma unroll
        for (int tm = 0; tm < 2; tm++)
#pragma unroll
            for (int nt = 0; nt < 8; nt++) {
                int col = n0 + wn + nt * 8 + (lane & 3) * 2;
#pragma unroll
                for (int half = 0; half < 2; half++) {
                    int row = m0 + wm + tm * 16 + (lane >> 2) + half * 8;
                    float2 v = make_float2(acc[tm][nt][half * 2],
                                           acc[tm][nt][half * 2 + 1]);
                    *(float2*)&C[(size_t)row * NC + col] = v;
                }
            }
    }
}

// ---------------------------------------------------------------------------
// Flash attention, bf16x3 mma. CTA = (b, h, 128 q rows), 8 warps (16 q rows
// each), kv tiles of 64. P fragments built directly from S accumulators.
// ---------------------------------------------------------------------------
__global__ __launch_bounds__(256) void attn_mma() {
    extern __shared__ __nv_bfloat16 sm[];
    __nv_bfloat16* Qh = sm;                  // [128][72]
    __nv_bfloat16* Ql = Qh + 128 * 72;
    __nv_bfloat16* Kh = Ql + 128 * 72;       // [64][72]  (natural [s][d])
    __nv_bfloat16* Kl = Kh + 64 * 72;
    __nv_bfloat16* Vh = Kl + 64 * 72;        // [64][72]
    __nv_bfloat16* Vl = Vh + 64 * 72;

    const int tid = threadIdx.x, lane = tid & 31, w = tid >> 5;
    const int q0 = blockIdx.x * 128, h = blockIdx.y, b = blockIdx.z;
    const size_t hb = (size_t)(b * HH + h) * SS * DD;

    const uint32_t uQh = (uint32_t)__cvta_generic_to_shared(Qh);
    const uint32_t uQl = (uint32_t)__cvta_generic_to_shared(Ql);
    const uint32_t uKh = (uint32_t)__cvta_generic_to_shared(Kh);
    const uint32_t uKl = (uint32_t)__cvta_generic_to_shared(Kl);
    const uint32_t uVh = (uint32_t)__cvta_generic_to_shared(Vh);
    const uint32_t uVl = (uint32_t)__cvta_generic_to_shared(Vl);

    const int lm_r = lane & 15, lm_c = (lane >> 4) * 8;          // A / trans-B map
    const int bn_r = (lane & 7) + (lane >> 4) * 8;               // non-trans B map
    const int bn_c = ((lane >> 3) & 1) * 8;

    // Load Q tile (128 x 64) hi/lo
#pragma unroll
    for (int i = 0; i < 4; i++) {
        int idx = tid + i * 256;     // 0..1023
        int r = idx >> 3, c8 = (idx & 7) * 8;
        size_t src = hb + (size_t)(q0 + r) * DD + c8;
        *(int4*)&Qh[r * 72 + c8] = *(const int4*)(g_qh + src);
        *(int4*)&Ql[r * 72 + c8] = *(const int4*)(g_ql + src);
    }

    float m1 = -1.0e30f, m2 = -1.0e30f, l1 = 0.0f, l2 = 0.0f;
    float oacc[8][4];
#pragma unroll
    for (int j = 0; j < 8; j++)
#pragma unroll
        for (int q = 0; q < 4; q++) oacc[j][q] = 0.0f;

    for (int kv = 0; kv < SS; kv += 64) {
        __syncthreads();
#pragma unroll
        for (int i = 0; i < 2; i++) {
            int idx = tid + i * 256;  // 0..511
            int r = idx >> 3, c8 = (idx & 7) * 8;
            size_t src = hb + (size_t)(kv + r) * DD + c8;
            *(int4*)&Kh[r * 72 + c8] = *(const int4*)(g_kh + src);
            *(int4*)&Kl[r * 72 + c8] = *(const int4*)(g_kl + src);
            *(int4*)&Vh[r * 72 + c8] = *(const int4*)(g_vh + src);
            *(int4*)&Vl[r * 72 + c8] = *(const int4*)(g_vl + src);
        }
        __syncthreads();

        // S = Q @ K^T  (scale folded into Q)
        float sacc[8][4];
#pragma unroll
        for (int j = 0; j < 8; j++)
#pragma unroll
            for (int q = 0; q < 4; q++) sacc[j][q] = 0.0f;

#pragma unroll
        for (int kt = 0; kt < 4; kt++) {
            unsigned ah[4], al[4];
            uint32_t qoff = ((w * 16 + lm_r) * 72 + kt * 16 + lm_c) * 2;
            ldsm4(ah, uQh + qoff);
            ldsm4(al, uQl + qoff);
#pragma unroll
            for (int g = 0; g < 4; g++) {
                unsigned bh[4], bl[4];
                uint32_t koff = ((g * 16 + bn_r) * 72 + kt * 16 + bn_c) * 2;
                ldsm4(bh, uKh + koff);
                ldsm4(bl, uKl + koff);
                mma_bf16(sacc[2 * g],     ah, &bh[0]);
                mma_bf16(sacc[2 * g],     ah, &bl[0]);
                mma_bf16(sacc[2 * g],     al, &bh[0]);
                mma_bf16(sacc[2 * g + 1], ah, &bh[2]);
                mma_bf16(sacc[2 * g + 1], ah, &bl[2]);
                mma_bf16(sacc[2 * g + 1], al, &bh[2]);
            }
        }

        // Online softmax: rows r1 = w*16 + lane>>2 (regs 0,1) and r1+8 (regs 2,3)
        float mx1 = -1.0e30f, mx2 = -1.0e30f;
#pragma unroll
        for (int nt = 0; nt < 8; nt++) {
            mx1 = fmaxf(mx1, fmaxf(sacc[nt][0], sacc[nt][1]));
            mx2 = fmaxf(mx2, fmaxf(sacc[nt][2], sacc[nt][3]));
        }
#pragma unroll
        for (int off = 1; off <= 2; off <<= 1) {
            mx1 = fmaxf(mx1, __shfl_xor_sync(0xffffffffu, mx1, off));
            mx2 = fmaxf(mx2, __shfl_xor_sync(0xffffffffu, mx2, off));
        }
        float mn1 = fmaxf(m1, mx1), mn2 = fmaxf(m2, mx2);
        float fac1 = __expf(m1 - mn1), fac2 = __expf(m2 - mn2);
        float rs1 = 0.0f, rs2 = 0.0f;
#pragma unroll
        for (int nt = 0; nt < 8; nt++) {
            sacc[nt][0] = __expf(sacc[nt][0] - mn1);
            sacc[nt][1] = __expf(sacc[nt][1] - mn1);
            sacc[nt][2] = __expf(sacc[nt][2] - mn2);
            sacc[nt][3] = __expf(sacc[nt][3] - mn2);
            rs1 += sacc[nt][0] + sacc[nt][1];
            rs2 += sacc[nt][2] + sacc[nt][3];
        }
#pragma unroll
        for (int off = 1; off <= 2; off <<= 1) {
            rs1 += __shfl_xor_sync(0xffffffffu, rs1, off);
            rs2 += __shfl_xor_sync(0xffffffffu, rs2, off);
        }
        l1 = l1 * fac1 + rs1;
        l2 = l2 * fac2 + rs2;
        m1 = mn1;
        m2 = mn2;
#pragma unroll
        for (int nt = 0; nt < 8; nt++) {
            oacc[nt][0] *= fac1;
            oacc[nt][1] *= fac1;
            oacc[nt][2] *= fac2;
            oacc[nt][3] *= fac2;
        }

        // Build P fragments (hi/lo) directly from sacc registers
        unsigned ph[4][4], pl[4][4];
#pragma unroll
        for (int kt = 0; kt < 4; kt++) {
            split_pair(sacc[2 * kt][0],     sacc[2 * kt][1],     ph[kt][0], pl[kt][0]);
            split_pair(sacc[2 * kt][2],     sacc[2 * kt][3],     ph[kt][1], pl[kt][1]);
            split_pair(sacc[2 * kt + 1][0], sacc[2 * kt + 1][1], ph[kt][2], pl[kt][2]);
            split_pair(sacc[2 * kt + 1][2], sacc[2 * kt + 1][3], ph[kt][3], pl[kt][3]);
        }

        // O += P @ V
#pragma unroll
        for (int kt = 0; kt < 4; kt++) {
#pragma unroll
            for (int dg = 0; dg < 4; dg++) {
                unsigned vh[4], vl[4];
                uint32_t voff = ((kt * 16 + lm_r) * 72 + dg * 16 + lm_c) * 2;
                ldsm4t(vh, uVh + voff);
                ldsm4t(vl, uVl + voff);
                mma_bf16(oacc[2 * dg],     ph[kt], &vh[0]);
                mma_bf16(oacc[2 * dg],     ph[kt], &vl[0]);
                mma_bf16(oacc[2 * dg],     pl[kt], &vh[0]);
                mma_bf16(oacc[2 * dg + 1], ph[kt], &vh[2]);
                mma_bf16(oacc[2 * dg + 1], ph[kt], &vl[2]);
                mma_bf16(oacc[2 * dg + 1], pl[kt], &vh[2]);
            }
        }
    }

    // Epilogue: normalize and store O as bf16 hi/lo to g_oh/g_ol [(b,s)][h*64+d]
    float inv1 = 1.0f / l1, inv2 = 1.0f / l2;
    int r1 = q0 + w * 16 + (lane >> 2);
#pragma unroll
    for (int nt = 0; nt < 8; nt++) {
        int d = nt * 8 + (lane & 3) * 2;
        unsigned hi, lo;
        split_pair(oacc[nt][0] * inv1, oacc[nt][1] * inv1, hi, lo);
        size_t off = ((size_t)(b * SS + r1)) * EE + h * DD + d;
        *(unsigned*)&g_oh[off] = hi;
        *(unsigned*)&g_ol[off] = lo;
        split_pair(oacc[nt][2] * inv2, oacc[nt][3] * inv2, hi, lo);
        off = ((size_t)(b * SS + r1 + 8)) * EE + h * DD + d;
        *(unsigned*)&g_oh[off] = hi;
        *(unsigned*)&g_ol[off] = lo;
    }
}

// ---------------------------------------------------------------------------
extern "C" void kernel_launch(void* const* d_in, const int* in_sizes, int n_in,
                              void* d_out, int out_size) {
    const float* x = (const float*)d_in[0];      // (B, S, E)
    const float* w_qkv = (const float*)d_in[1];  // (E, 3E)
    const float* w_out = (const float*)d_in[2];  // (E, E)
    float* out = (float*)d_out;                  // (B, S, E)

    // 1) QKV projection (bf16x3), scatter Q/K/V hi/lo (Q pre-scaled)
    mma_gemm<NQKV, false>
        <<<dim3(NQKV / 128, (BB * SS) / 128), 256>>>(x, w_qkv, nullptr);

    // 2) Flash attention (bf16x3 mma)
    const int smem_bytes = (2 * 128 * 72 + 4 * 64 * 72) * (int)sizeof(__nv_bfloat16);
    cudaFuncSetAttribute(attn_mma, cudaFuncAttributeMaxDynamicSharedMemorySize,
                         smem_bytes);
    attn_mma<<<dim3(SS / 128, HH, BB), 256, smem_bytes>>>();

    // 3) Output projection (bf16x3), A = O hi/lo
    mma_gemm<EE, true>
        <<<dim3(EE / 128, (BB * SS) / 128), 256>>>(nullptr, w_out, out);
}

// round 4
// speedup vs baseline: 2.5598x; 1.5723x over previous
#include <cuda_runtime.h>
#include <cuda_bf16.h>
#include <cstdint>
#include <math.h>

#define BB 2
#define SS 2048
#define EE 1024
#define HH 16
#define DD 64
#define NQKV 3072

// ---------------------------------------------------------------------------
// Scratch (device globals — allocation-free)
// ---------------------------------------------------------------------------
__device__ __nv_bfloat16 g_xh[BB*SS*EE],  g_xl[BB*SS*EE];    // split x
__device__ __nv_bfloat16 g_wqh[EE*NQKV],  g_wql[EE*NQKV];    // split w_qkv
__device__ __nv_bfloat16 g_woh[EE*EE],    g_wol[EE*EE];      // split w_out
__device__ __nv_bfloat16 g_qh[BB*HH*SS*DD], g_ql[BB*HH*SS*DD];
__device__ __nv_bfloat16 g_kh[BB*HH*SS*DD], g_kl[BB*HH*SS*DD];
__device__ __nv_bfloat16 g_vh[BB*HH*SS*DD], g_vl[BB*HH*SS*DD];
__device__ __nv_bfloat16 g_oh[BB*SS*EE],    g_ol[BB*SS*EE];

// ---------------------------------------------------------------------------
// PTX wrappers
// ---------------------------------------------------------------------------
__device__ __forceinline__ void ldsm4(unsigned r[4], uint32_t a) {
    asm volatile("ldmatrix.sync.aligned.m8n8.x4.shared.b16 {%0,%1,%2,%3}, [%4];\n"
                 : "=r"(r[0]), "=r"(r[1]), "=r"(r[2]), "=r"(r[3]) : "r"(a));
}
__device__ __forceinline__ void ldsm4t(unsigned r[4], uint32_t a) {
    asm volatile("ldmatrix.sync.aligned.m8n8.x4.trans.shared.b16 {%0,%1,%2,%3}, [%4];\n"
                 : "=r"(r[0]), "=r"(r[1]), "=r"(r[2]), "=r"(r[3]) : "r"(a));
}
__device__ __forceinline__ void mma_bf16(float c[4], const unsigned a[4], const unsigned b[2]) {
    asm volatile(
        "mma.sync.aligned.m16n8k16.row.col.f32.bf16.bf16.f32 "
        "{%0,%1,%2,%3}, {%4,%5,%6,%7}, {%8,%9}, {%0,%1,%2,%3};\n"
        : "+f"(c[0]), "+f"(c[1]), "+f"(c[2]), "+f"(c[3])
        : "r"(a[0]), "r"(a[1]), "r"(a[2]), "r"(a[3]), "r"(b[0]), "r"(b[1]));
}
__device__ __forceinline__ void cp16(uint32_t s, const void* g) {
    asm volatile("cp.async.cg.shared.global [%0], [%1], 16;\n" :: "r"(s), "l"(g));
}
__device__ __forceinline__ void cp_commit() {
    asm volatile("cp.async.commit_group;\n" ::: "memory");
}
template <int N>
__device__ __forceinline__ void cp_wait() {
    asm volatile("cp.async.wait_group %0;\n" :: "n"(N) : "memory");
}
// split (x,y) fp32 pair into packed bf16x2 hi and lo (residual) words
__device__ __forceinline__ void split_pair(float x, float y, unsigned &hi, unsigned &lo) {
    __nv_bfloat162 h2 = __floats2bfloat162_rn(x, y);
    float xr = x - __bfloat162float(__low2bfloat16(h2));
    float yr = y - __bfloat162float(__high2bfloat16(h2));
    __nv_bfloat162 l2 = __floats2bfloat162_rn(xr, yr);
    hi = *reinterpret_cast<unsigned*>(&h2);
    lo = *reinterpret_cast<unsigned*>(&l2);
}

// ---------------------------------------------------------------------------
// Elementwise fp32 -> bf16 hi/lo split
// ---------------------------------------------------------------------------
__global__ __launch_bounds__(256) void split_kernel(const float* __restrict__ src,
                                                    __nv_bfloat16* __restrict__ dh,
                                                    __nv_bfloat16* __restrict__ dl,
                                                    int n4) {
    int i = blockIdx.x * 256 + threadIdx.x;
    if (i < n4) {
        float4 v = *(const float4*)(src + (size_t)i * 4);
        unsigned h0, l0, h1, l1;
        split_pair(v.x, v.y, h0, l0);
        split_pair(v.z, v.w, h1, l1);
        *(uint2*)(dh + (size_t)i * 4) = make_uint2(h0, h1);
        *(uint2*)(dl + (size_t)i * 4) = make_uint2(l0, l1);
    }
}

// ---------------------------------------------------------------------------
// bf16x3 GEMM, pre-split inputs, cp.async double-buffered.
// C[M, NC] = A[M,1024] @ W[1024,NC].  BM=128, BN=128, BK=32, 8 warps.
// SCATTER: epilogue scatters to g_q/k/v hi-lo (Q scaled); else fp32 C.
// smem: A[2buf][2hl][128*40], B[2buf][2hl][32*136]  (dynamic, 75776 B)
// ---------------------------------------------------------------------------
#define GA_STRIDE (128 * 40)
#define GB_STRIDE (32 * 136)
#define GB_BASE (4 * GA_STRIDE)

template <int NC, bool SCATTER>
__global__ __launch_bounds__(256) void mma_gemm2(const __nv_bfloat16* __restrict__ Ah_g,
                                                 const __nv_bfloat16* __restrict__ Al_g,
                                                 const __nv_bfloat16* __restrict__ Bh_g,
                                                 const __nv_bfloat16* __restrict__ Bl_g,
                                                 float* __restrict__ C) {
    extern __shared__ __align__(16) __nv_bfloat16 smem[];
    const int tid = threadIdx.x;
    const int lane = tid & 31, wid = tid >> 5;
    const int wm = (wid & 3) * 32, wn = (wid >> 2) * 64;
    const int m0 = blockIdx.y * 128, n0 = blockIdx.x * 128;

    const uint32_t uS = (uint32_t)__cvta_generic_to_shared(smem);

    const int lm_r = lane & 15, lm_c = (lane >> 4) * 8;

    // per-thread cp.async source/dest mapping
    const int a_r = tid >> 1, a_c8 = (tid & 1) * 16;          // 128 rows x 32 cols: 2 cp16/row/hl... 
    const int b_r = tid >> 4, b_c8 = (tid & 15) * 8;          // 32 rows x 128 cols

    // ldmatrix base offsets (add buf/hl/kk terms in loop)
    const uint32_t aoff0 = ((wm + lm_r) * 40 + lm_c) * 2;
    const uint32_t boff0 = (lm_r * 136 + wn + lm_c) * 2;

    float acc[2][8][4];
#pragma unroll
    for (int i = 0; i < 2; i++)
#pragma unroll
        for (int j = 0; j < 8; j++)
#pragma unroll
            for (int q = 0; q < 4; q++) acc[i][j][q] = 0.0f;

    auto load_tile = [&](int buf, int k0) {
        // A: 128x32 per hl: each thread 1 cp16 per hl at (a_r, a_c8..a_c8+7)? 
        // 128*32 = 4096 elems = 8192B = 512 cp16 per hl; 256 threads -> 2 each
        uint32_t abase = uS + (buf * 2) * GA_STRIDE * 2;
#pragma unroll
        for (int i = 0; i < 2; i++) {
            int idx = tid + i * 256;              // 0..511
            int r = idx >> 2, c8 = (idx & 3) * 8; // r 0..127, c8 0..24
            cp16(abase + (r * 40 + c8) * 2,
                 Ah_g + (size_t)(m0 + r) * EE + k0 + c8);
            cp16(abase + GA_STRIDE * 2 + (r * 40 + c8) * 2,
                 Al_g + (size_t)(m0 + r) * EE + k0 + c8);
        }
        // B: 32x128 per hl: 4096 elems -> 2 cp16/thread/hl
        uint32_t bbase = uS + (GB_BASE + (buf * 2) * GB_STRIDE) * 2;
#pragma unroll
        for (int i = 0; i < 2; i++) {
            int idx = tid + i * 256;
            int r = idx >> 4, c8 = (idx & 15) * 8; // r 0..31, c8 0..120
            cp16(bbase + (r * 136 + c8) * 2,
                 Bh_g + (size_t)(k0 + r) * NC + n0 + c8);
            cp16(bbase + GB_STRIDE * 2 + (r * 136 + c8) * 2,
                 Bl_g + (size_t)(k0 + r) * NC + n0 + c8);
        }
    };

    load_tile(0, 0);
    cp_commit();

#pragma unroll 1
    for (int kt = 0; kt < 32; kt++) {
        const int buf = kt & 1;
        if (kt + 1 < 32) load_tile(buf ^ 1, (kt + 1) * 32);
        cp_commit();
        if (kt + 1 < 32) cp_wait<1>(); else cp_wait<0>();
        __syncthreads();

        const uint32_t uAh = uS + (buf * 2) * GA_STRIDE * 2;
        const uint32_t uAl = uAh + GA_STRIDE * 2;
        const uint32_t uBh = uS + (GB_BASE + (buf * 2) * GB_STRIDE) * 2;
        const uint32_t uBl = uBh + GB_STRIDE * 2;

#pragma unroll
        for (int ks = 0; ks < 2; ks++) {
            const int kk = ks * 16;
            unsigned ah[2][4], al[2][4];
#pragma unroll
            for (int tm = 0; tm < 2; tm++) {
                uint32_t off = aoff0 + (tm * 16 * 40 + kk) * 2;
                ldsm4(ah[tm], uAh + off);
                ldsm4(al[tm], uAl + off);
            }
            unsigned bh[4][4], bl[4][4];
#pragma unroll
            for (int g = 0; g < 4; g++) {
                uint32_t off = boff0 + (kk * 136 + g * 16) * 2;
                ldsm4t(bh[g], uBh + off);
                ldsm4t(bl[g], uBl + off);
            }
#pragma unroll
            for (int tm = 0; tm < 2; tm++)
#pragma unroll
                for (int nt = 0; nt < 8; nt++) {
                    const unsigned* bhp = &bh[nt >> 1][(nt & 1) * 2];
                    const unsigned* blp = &bl[nt >> 1][(nt & 1) * 2];
                    mma_bf16(acc[tm][nt], ah[tm], bhp);
                    mma_bf16(acc[tm][nt], ah[tm], blp);
                    mma_bf16(acc[tm][nt], al[tm], bhp);
                }
        }
        __syncthreads();
    }

    if (SCATTER) {
#pragma unroll
        for (int tm = 0; tm < 2; tm++)
#pragma unroll
            for (int nt = 0; nt < 8; nt++) {
                int f = n0 + wn + nt * 8 + (lane & 3) * 2;
                int cid = f >> 10;
                int hh = (f >> 6) & (HH - 1);
                int d = f & (DD - 1);
                float sc = (cid == 0) ? 0.125f : 1.0f;
                __nv_bfloat16* dh = (cid == 0) ? g_qh : (cid == 1) ? g_kh : g_vh;
                __nv_bfloat16* dl = (cid == 0) ? g_ql : (cid == 1) ? g_kl : g_vl;
#pragma unroll
                for (int half = 0; half < 2; half++) {
                    int row = m0 + wm + tm * 16 + (lane >> 2) + half * 8;
                    int b = row >> 11, s = row & (SS - 1);
                    size_t off = ((size_t)((b * HH + hh) * SS + s)) * DD + d;
                    unsigned hi, lo;
                    split_pair(acc[tm][nt][half * 2] * sc,
                               acc[tm][nt][half * 2 + 1] * sc, hi, lo);
                    *(unsigned*)&dh[off] = hi;
                    *(unsigned*)&dl[off] = lo;
                }
            }
    } else {
#pragma unroll
        for (int tm = 0; tm < 2; tm++)
#pragma unroll
            for (int nt = 0; nt < 8; nt++) {
                int col = n0 + wn + nt * 8 + (lane & 3) * 2;
#pragma unroll
                for (int half = 0; half < 2; half++) {
                    int row = m0 + wm + tm * 16 + (lane >> 2) + half * 8;
                    float2 v = make_float2(acc[tm][nt][half * 2],
                                           acc[tm][nt][half * 2 + 1]);
                    *(float2*)&C[(size_t)row * NC + col] = v;
                }
            }
    }
}

// ---------------------------------------------------------------------------
// Flash attention, bf16x3 mma, cp.async double-buffered K/V.
// CTA = (b, h, 128 q rows), 8 warps, kv tiles of 64.
// smem elems: Qh[128*72], Ql[128*72], KV[2buf][4 tensors][64*72]
// ---------------------------------------------------------------------------
#define AT_Q 9216            // 128*72
#define AT_T 4608            // 64*72
#define AT_KV (2 * AT_Q)

__global__ __launch_bounds__(256) void attn_mma2() {
    extern __shared__ __align__(16) __nv_bfloat16 smem[];
    const int tid = threadIdx.x, lane = tid & 31, w = tid >> 5;
    const int q0 = blockIdx.x * 128, h = blockIdx.y, b = blockIdx.z;
    const size_t hb = (size_t)(b * HH + h) * SS * DD;

    const uint32_t uS = (uint32_t)__cvta_generic_to_shared(smem);
    const uint32_t uQh = uS, uQl = uS + AT_Q * 2;

    const int lm_r = lane & 15, lm_c = (lane >> 4) * 8;
    const int bn_r = (lane & 7) + (lane >> 4) * 8;
    const int bn_c = ((lane >> 3) & 1) * 8;

    auto kv_base = [&](int buf, int t) -> uint32_t {
        return uS + (AT_KV + (buf * 4 + t) * AT_T) * 2;
    };

    auto load_kv = [&](int buf, int kv) {
        const __nv_bfloat16* s0 = g_kh + hb + (size_t)kv * DD;
        const __nv_bfloat16* s1 = g_kl + hb + (size_t)kv * DD;
        const __nv_bfloat16* s2 = g_vh + hb + (size_t)kv * DD;
        const __nv_bfloat16* s3 = g_vl + hb + (size_t)kv * DD;
#pragma unroll
        for (int i = 0; i < 2; i++) {
            int idx = tid + i * 256;               // 0..511
            int r = idx >> 3, c8 = (idx & 7) * 8;  // r 0..63, c8 0..56
            uint32_t so = (r * 72 + c8) * 2;
            int go = r * DD + c8;
            cp16(kv_base(buf, 0) + so, s0 + go);
            cp16(kv_base(buf, 1) + so, s1 + go);
            cp16(kv_base(buf, 2) + so, s2 + go);
            cp16(kv_base(buf, 3) + so, s3 + go);
        }
    };

    // group 0: Q + first KV tile
#pragma unroll
    for (int i = 0; i < 4; i++) {
        int idx = tid + i * 256;                   // 0..1023
        int r = idx >> 3, c8 = (idx & 7) * 8;      // r 0..127
        uint32_t so = (r * 72 + c8) * 2;
        size_t go = hb + (size_t)(q0 + r) * DD + c8;
        cp16(uQh + so, g_qh + go);
        cp16(uQl + so, g_ql + go);
    }
    load_kv(0, 0);
    cp_commit();

    float m1 = -1.0e30f, m2 = -1.0e30f, l1 = 0.0f, l2 = 0.0f;
    float oacc[8][4];
#pragma unroll
    for (int j = 0; j < 8; j++)
#pragma unroll
        for (int q = 0; q < 4; q++) oacc[j][q] = 0.0f;

#pragma unroll 1
    for (int ti = 0; ti < 32; ti++) {
        const int buf = ti & 1;
        if (ti + 1 < 32) load_kv(buf ^ 1, (ti + 1) * 64);
        cp_commit();
        if (ti + 1 < 32) cp_wait<1>(); else cp_wait<0>();
        __syncthreads();

        const uint32_t uKh = kv_base(buf, 0), uKl = kv_base(buf, 1);
        const uint32_t uVh = kv_base(buf, 2), uVl = kv_base(buf, 3);

        // S = Q @ K^T  (scale folded into Q)
        float sacc[8][4];
#pragma unroll
        for (int j = 0; j < 8; j++)
#pragma unroll
            for (int q = 0; q < 4; q++) sacc[j][q] = 0.0f;

#pragma unroll
        for (int kt = 0; kt < 4; kt++) {
            unsigned ah[4], al[4];
            uint32_t qoff = ((w * 16 + lm_r) * 72 + kt * 16 + lm_c) * 2;
            ldsm4(ah, uQh + qoff);
            ldsm4(al, uQl + qoff);
#pragma unroll
            for (int g = 0; g < 4; g++) {
                unsigned bh[4], bl[4];
                uint32_t koff = ((g * 16 + bn_r) * 72 + kt * 16 + bn_c) * 2;
                ldsm4(bh, uKh + koff);
                ldsm4(bl, uKl + koff);
                mma_bf16(sacc[2 * g],     ah, &bh[0]);
                mma_bf16(sacc[2 * g],     ah, &bl[0]);
                mma_bf16(sacc[2 * g],     al, &bh[0]);
                mma_bf16(sacc[2 * g + 1], ah, &bh[2]);
                mma_bf16(sacc[2 * g + 1], ah, &bl[2]);
                mma_bf16(sacc[2 * g + 1], al, &bh[2]);
            }
        }

        // Online softmax
        float mx1 = -1.0e30f, mx2 = -1.0e30f;
#pragma unroll
        for (int nt = 0; nt < 8; nt++) {
            mx1 = fmaxf(mx1, fmaxf(sacc[nt][0], sacc[nt][1]));
            mx2 = fmaxf(mx2, fmaxf(sacc[nt][2], sacc[nt][3]));
        }
#pragma unroll
        for (int off = 1; off <= 2; off <<= 1) {
            mx1 = fmaxf(mx1, __shfl_xor_sync(0xffffffffu, mx1, off));
            mx2 = fmaxf(mx2, __shfl_xor_sync(0xffffffffu, mx2, off));
        }
        float mn1 = fmaxf(m1, mx1), mn2 = fmaxf(m2, mx2);
        float fac1 = __expf(m1 - mn1), fac2 = __expf(m2 - mn2);
        float rs1 = 0.0f, rs2 = 0.0f;
#pragma unroll
        for (int nt = 0; nt < 8; nt++) {
            sacc[nt][0] = __expf(sacc[nt][0] - mn1);
            sacc[nt][1] = __expf(sacc[nt][1] - mn1);
            sacc[nt][2] = __expf(sacc[nt][2] - mn2);
            sacc[nt][3] = __expf(sacc[nt][3] - mn2);
            rs1 += sacc[nt][0] + sacc[nt][1];
            rs2 += sacc[nt][2] + sacc[nt][3];
        }
#pragma unroll
        for (int off = 1; off <= 2; off <<= 1) {
            rs1 += __shfl_xor_sync(0xffffffffu, rs1, off);
            rs2 += __shfl_xor_sync(0xffffffffu, rs2, off);
        }
        l1 = l1 * fac1 + rs1;
        l2 = l2 * fac2 + rs2;
        m1 = mn1;
        m2 = mn2;
#pragma unroll
        for (int nt = 0; nt < 8; nt++) {
            oacc[nt][0] *= fac1;
            oacc[nt][1] *= fac1;
            oacc[nt][2] *= fac2;
            oacc[nt][3] *= fac2;
        }

        // P fragments (hi/lo) straight from sacc registers
        unsigned ph[4][4], pl[4][4];
#pragma unroll
        for (int kt = 0; kt < 4; kt++) {
            split_pair(sacc[2 * kt][0],     sacc[2 * kt][1],     ph[kt][0], pl[kt][0]);
            split_pair(sacc[2 * kt][2],     sacc[2 * kt][3],     ph[kt][1], pl[kt][1]);
            split_pair(sacc[2 * kt + 1][0], sacc[2 * kt + 1][1], ph[kt][2], pl[kt][2]);
            split_pair(sacc[2 * kt + 1][2], sacc[2 * kt + 1][3], ph[kt][3], pl[kt][3]);
        }

        // O += P @ V
#pragma unroll
        for (int kt = 0; kt < 4; kt++) {
#pragma unroll
            for (int dg = 0; dg < 4; dg++) {
                unsigned vh[4], vl[4];
                uint32_t voff = ((kt * 16 + lm_r) * 72 + dg * 16 + lm_c) * 2;
                ldsm4t(vh, uVh + voff);
                ldsm4t(vl, uVl + voff);
                mma_bf16(oacc[2 * dg],     ph[kt], &vh[0]);
                mma_bf16(oacc[2 * dg],     ph[kt], &vl[0]);
                mma_bf16(oacc[2 * dg],     pl[kt], &vh[0]);
                mma_bf16(oacc[2 * dg + 1], ph[kt], &vh[2]);
                mma_bf16(oacc[2 * dg + 1], ph[kt], &vl[2]);
                mma_bf16(oacc[2 * dg + 1], pl[kt], &vh[2]);
            }
        }
        __syncthreads();
    }

    // normalize + store O hi/lo
    float inv1 = 1.0f / l1, inv2 = 1.0f / l2;
    int r1 = q0 + w * 16 + (lane >> 2);
#pragma unroll
    for (int nt = 0; nt < 8; nt++) {
        int d = nt * 8 + (lane & 3) * 2;
        unsigned hi, lo;
        split_pair(oacc[nt][0] * inv1, oacc[nt][1] * inv1, hi, lo);
        size_t off = ((size_t)(b * SS + r1)) * EE + h * DD + d;
        *(unsigned*)&g_oh[off] = hi;
        *(unsigned*)&g_ol[off] = lo;
        split_pair(oacc[nt][2] * inv2, oacc[nt][3] * inv2, hi, lo);
        off = ((size_t)(b * SS + r1 + 8)) * EE + h * DD + d;
        *(unsigned*)&g_oh[off] = hi;
        *(unsigned*)&g_ol[off] = lo;
    }
}

// ---------------------------------------------------------------------------
extern "C" void kernel_launch(void* const* d_in, const int* in_sizes, int n_in,
                              void* d_out, int out_size) {
    const float* x = (const float*)d_in[0];      // (B, S, E)
    const float* w_qkv = (const float*)d_in[1];  // (E, 3E)
    const float* w_out = (const float*)d_in[2];  // (E, E)
    float* out = (float*)d_out;                  // (B, S, E)

    __nv_bfloat16 *p_xh, *p_xl, *p_wqh, *p_wql, *p_woh, *p_wol;
    __nv_bfloat16 *p_oh, *p_ol;
    cudaGetSymbolAddress((void**)&p_xh, g_xh);
    cudaGetSymbolAddress((void**)&p_xl, g_xl);
    cudaGetSymbolAddress((void**)&p_wqh, g_wqh);
    cudaGetSymbolAddress((void**)&p_wql, g_wql);
    cudaGetSymbolAddress((void**)&p_woh, g_woh);
    cudaGetSymbolAddress((void**)&p_wol, g_wol);
    cudaGetSymbolAddress((void**)&p_oh, g_oh);
    cudaGetSymbolAddress((void**)&p_ol, g_ol);

    // 0) split inputs once
    split_kernel<<<(BB*SS*EE/4 + 255) / 256, 256>>>(x, p_xh, p_xl, BB*SS*EE/4);
    split_kernel<<<(EE*NQKV/4 + 255) / 256, 256>>>(w_qkv, p_wqh, p_wql, EE*NQKV/4);
    split_kernel<<<(EE*EE/4 + 255) / 256, 256>>>(w_out, p_woh, p_wol, EE*EE/4);

    const int gemm_smem = (4 * GA_STRIDE + 4 * GB_STRIDE) * (int)sizeof(__nv_bfloat16);

    // 1) QKV projection, scatter Q/K/V hi/lo (Q pre-scaled)
    cudaFuncSetAttribute(mma_gemm2<NQKV, true>,
                         cudaFuncAttributeMaxDynamicSharedMemorySize, gemm_smem);
    mma_gemm2<NQKV, true><<<dim3(NQKV / 128, (BB * SS) / 128), 256, gemm_smem>>>(
        p_xh, p_xl, p_wqh, p_wql, nullptr);

    // 2) Flash attention
    const int attn_smem = (AT_KV + 8 * AT_T) * (int)sizeof(__nv_bfloat16);
    cudaFuncSetAttribute(attn_mma2, cudaFuncAttributeMaxDynamicSharedMemorySize,
                         attn_smem);
    attn_mma2<<<dim3(SS / 128, HH, BB), 256, attn_smem>>>();

    // 3) Output projection
    cudaFuncSetAttribute(mma_gemm2<EE, false>,
                         cudaFuncAttributeMaxDynamicSharedMemorySize, gemm_smem);
    mma_gemm2<EE, false><<<dim3(EE / 128, (BB * SS) / 128), 256, gemm_smem>>>(
        p_oh, p_ol, p_woh, p_wol, out);
}

// round 5
// speedup vs baseline: 2.8088x; 1.0973x over previous
#include <cuda_runtime.h>
#include <cuda_bf16.h>
#include <cstdint>
#include <math.h>

#define BB 2
#define SS 2048
#define EE 1024
#define HH 16
#define DD 64
#define NQKV 3072

// ---------------------------------------------------------------------------
// Scratch (device globals — allocation-free)
// ---------------------------------------------------------------------------
__device__ __nv_bfloat16 g_xh[BB*SS*EE],  g_xl[BB*SS*EE];    // split x
__device__ __nv_bfloat16 g_wqh[EE*NQKV],  g_wql[EE*NQKV];    // split w_qkv
__device__ __nv_bfloat16 g_woh[EE*EE],    g_wol[EE*EE];      // split w_out
__device__ __nv_bfloat16 g_qh[BB*HH*SS*DD], g_ql[BB*HH*SS*DD];
__device__ __nv_bfloat16 g_kh[BB*HH*SS*DD], g_kl[BB*HH*SS*DD];
__device__ __nv_bfloat16 g_vh[BB*HH*SS*DD], g_vl[BB*HH*SS*DD];
__device__ __nv_bfloat16 g_oh[BB*SS*EE],    g_ol[BB*SS*EE];

// ---------------------------------------------------------------------------
// PTX wrappers
// ---------------------------------------------------------------------------
__device__ __forceinline__ void ldsm4(unsigned r[4], uint32_t a) {
    asm volatile("ldmatrix.sync.aligned.m8n8.x4.shared.b16 {%0,%1,%2,%3}, [%4];\n"
                 : "=r"(r[0]), "=r"(r[1]), "=r"(r[2]), "=r"(r[3]) : "r"(a));
}
__device__ __forceinline__ void ldsm4t(unsigned r[4], uint32_t a) {
    asm volatile("ldmatrix.sync.aligned.m8n8.x4.trans.shared.b16 {%0,%1,%2,%3}, [%4];\n"
                 : "=r"(r[0]), "=r"(r[1]), "=r"(r[2]), "=r"(r[3]) : "r"(a));
}
__device__ __forceinline__ void mma_bf16(float c[4], const unsigned a[4], const unsigned b[2]) {
    asm volatile(
        "mma.sync.aligned.m16n8k16.row.col.f32.bf16.bf16.f32 "
        "{%0,%1,%2,%3}, {%4,%5,%6,%7}, {%8,%9}, {%0,%1,%2,%3};\n"
        : "+f"(c[0]), "+f"(c[1]), "+f"(c[2]), "+f"(c[3])
        : "r"(a[0]), "r"(a[1]), "r"(a[2]), "r"(a[3]), "r"(b[0]), "r"(b[1]));
}
__device__ __forceinline__ void cp16(uint32_t s, const void* g) {
    asm volatile("cp.async.cg.shared.global [%0], [%1], 16;\n" :: "r"(s), "l"(g));
}
__device__ __forceinline__ void cp_commit() {
    asm volatile("cp.async.commit_group;\n" ::: "memory");
}
template <int N>
__device__ __forceinline__ void cp_wait() {
    asm volatile("cp.async.wait_group %0;\n" :: "n"(N) : "memory");
}
// split (x,y) fp32 pair into packed bf16x2 hi and lo (residual) words
__device__ __forceinline__ void split_pair(float x, float y, unsigned &hi, unsigned &lo) {
    __nv_bfloat162 h2 = __floats2bfloat162_rn(x, y);
    float xr = x - __bfloat162float(__low2bfloat16(h2));
    float yr = y - __bfloat162float(__high2bfloat16(h2));
    __nv_bfloat162 l2 = __floats2bfloat162_rn(xr, yr);
    hi = *reinterpret_cast<unsigned*>(&h2);
    lo = *reinterpret_cast<unsigned*>(&l2);
}

// ---------------------------------------------------------------------------
// Elementwise fp32 -> bf16 hi/lo split
// ---------------------------------------------------------------------------
__global__ __launch_bounds__(256) void split_kernel(const float* __restrict__ src,
                                                    __nv_bfloat16* __restrict__ dh,
                                                    __nv_bfloat16* __restrict__ dl,
                                                    int n4) {
    int i = blockIdx.x * 256 + threadIdx.x;
    if (i < n4) {
        float4 v = *(const float4*)(src + (size_t)i * 4);
        unsigned h0, l0, h1, l1;
        split_pair(v.x, v.y, h0, l0);
        split_pair(v.z, v.w, h1, l1);
        *(uint2*)(dh + (size_t)i * 4) = make_uint2(h0, h1);
        *(uint2*)(dl + (size_t)i * 4) = make_uint2(l0, l1);
    }
}

// ---------------------------------------------------------------------------
// bf16x3 GEMM, pre-split inputs, cp.async double-buffered, 2 CTAs/SM.
// C[M, NC] = A[M,1024] @ W[1024,NC].  BM=128, BN=128, BK=32, 8 warps.
// ---------------------------------------------------------------------------
#define GA_STRIDE (128 * 40)
#define GB_STRIDE (32 * 136)
#define GB_BASE (4 * GA_STRIDE)

template <int NC, bool SCATTER>
__global__ __launch_bounds__(256, 2) void mma_gemm2(const __nv_bfloat16* __restrict__ Ah_g,
                                                    const __nv_bfloat16* __restrict__ Al_g,
                                                    const __nv_bfloat16* __restrict__ Bh_g,
                                                    const __nv_bfloat16* __restrict__ Bl_g,
                                                    float* __restrict__ C) {
    extern __shared__ __align__(16) __nv_bfloat16 smem[];
    const int tid = threadIdx.x;
    const int lane = tid & 31, wid = tid >> 5;
    const int wm = (wid & 3) * 32, wn = (wid >> 2) * 64;
    const int m0 = blockIdx.y * 128, n0 = blockIdx.x * 128;

    const uint32_t uS = (uint32_t)__cvta_generic_to_shared(smem);

    const int lm_r = lane & 15, lm_c = (lane >> 4) * 8;

    // ldmatrix base offsets (add buf/kk/g terms in loop)
    const uint32_t aoff0 = ((wm + lm_r) * 40 + lm_c) * 2;
    const uint32_t boff0 = (lm_r * 136 + wn + lm_c) * 2;

    float acc[2][8][4];
#pragma unroll
    for (int i = 0; i < 2; i++)
#pragma unroll
        for (int j = 0; j < 8; j++)
#pragma unroll
            for (int q = 0; q < 4; q++) acc[i][j][q] = 0.0f;

    auto load_tile = [&](int buf, int k0) {
        uint32_t abase = uS + (buf * 2) * GA_STRIDE * 2;
#pragma unroll
        for (int i = 0; i < 2; i++) {
            int idx = tid + i * 256;              // 0..511
            int r = idx >> 2, c8 = (idx & 3) * 8; // r 0..127, c8 0..24
            cp16(abase + (r * 40 + c8) * 2,
                 Ah_g + (size_t)(m0 + r) * EE + k0 + c8);
            cp16(abase + GA_STRIDE * 2 + (r * 40 + c8) * 2,
                 Al_g + (size_t)(m0 + r) * EE + k0 + c8);
        }
        uint32_t bbase = uS + (GB_BASE + (buf * 2) * GB_STRIDE) * 2;
#pragma unroll
        for (int i = 0; i < 2; i++) {
            int idx = tid + i * 256;
            int r = idx >> 4, c8 = (idx & 15) * 8; // r 0..31, c8 0..120
            cp16(bbase + (r * 136 + c8) * 2,
                 Bh_g + (size_t)(k0 + r) * NC + n0 + c8);
            cp16(bbase + GB_STRIDE * 2 + (r * 136 + c8) * 2,
                 Bl_g + (size_t)(k0 + r) * NC + n0 + c8);
        }
    };

    load_tile(0, 0);
    cp_commit();

#pragma unroll 1
    for (int kt = 0; kt < 32; kt++) {
        const int buf = kt & 1;
        if (kt + 1 < 32) load_tile(buf ^ 1, (kt + 1) * 32);
        cp_commit();
        if (kt + 1 < 32) cp_wait<1>(); else cp_wait<0>();
        __syncthreads();

        const uint32_t uAh = uS + (buf * 2) * GA_STRIDE * 2;
        const uint32_t uAl = uAh + GA_STRIDE * 2;
        const uint32_t uBh = uS + (GB_BASE + (buf * 2) * GB_STRIDE) * 2;
        const uint32_t uBl = uBh + GB_STRIDE * 2;

#pragma unroll
        for (int ks = 0; ks < 2; ks++) {
            const int kk = ks * 16;
            unsigned ah[2][4], al[2][4];
#pragma unroll
            for (int tm = 0; tm < 2; tm++) {
                uint32_t off = aoff0 + (tm * 16 * 40 + kk) * 2;
                ldsm4(ah[tm], uAh + off);
                ldsm4(al[tm], uAl + off);
            }
            // Stream B fragments one 16-col group at a time (saves ~24 regs)
#pragma unroll
            for (int g = 0; g < 4; g++) {
                unsigned bh[4], bl[4];
                uint32_t off = boff0 + (kk * 136 + g * 16) * 2;
                ldsm4t(bh, uBh + off);
                ldsm4t(bl, uBl + off);
#pragma unroll
                for (int tm = 0; tm < 2; tm++) {
                    mma_bf16(acc[tm][2 * g],     ah[tm], &bh[0]);
                    mma_bf16(acc[tm][2 * g],     ah[tm], &bl[0]);
                    mma_bf16(acc[tm][2 * g],     al[tm], &bh[0]);
                    mma_bf16(acc[tm][2 * g + 1], ah[tm], &bh[2]);
                    mma_bf16(acc[tm][2 * g + 1], ah[tm], &bl[2]);
                    mma_bf16(acc[tm][2 * g + 1], al[tm], &bh[2]);
                }
            }
        }
        __syncthreads();
    }

    if (SCATTER) {
#pragma unroll
        for (int tm = 0; tm < 2; tm++)
#pragma unroll
            for (int nt = 0; nt < 8; nt++) {
                int f = n0 + wn + nt * 8 + (lane & 3) * 2;
                int cid = f >> 10;
                int hh = (f >> 6) & (HH - 1);
                int d = f & (DD - 1);
                float sc = (cid == 0) ? 0.125f : 1.0f;
                __nv_bfloat16* dh = (cid == 0) ? g_qh : (cid == 1) ? g_kh : g_vh;
                __nv_bfloat16* dl = (cid == 0) ? g_ql : (cid == 1) ? g_kl : g_vl;
#pragma unroll
                for (int half = 0; half < 2; half++) {
                    int row = m0 + wm + tm * 16 + (lane >> 2) + half * 8;
                    int b = row >> 11, s = row & (SS - 1);
                    size_t off = ((size_t)((b * HH + hh) * SS + s)) * DD + d;
                    unsigned hi, lo;
                    split_pair(acc[tm][nt][half * 2] * sc,
                               acc[tm][nt][half * 2 + 1] * sc, hi, lo);
                    *(unsigned*)&dh[off] = hi;
                    *(unsigned*)&dl[off] = lo;
                }
            }
    } else {
#pragma unroll
        for (int tm = 0; tm < 2; tm++)
#pragma unroll
            for (int nt = 0; nt < 8; nt++) {
                int col = n0 + wn + nt * 8 + (lane & 3) * 2;
#pragma unroll
                for (int half = 0; half < 2; half++) {
                    int row = m0 + wm + tm * 16 + (lane >> 2) + half * 8;
                    float2 v = make_float2(acc[tm][nt][half * 2],
                                           acc[tm][nt][half * 2 + 1]);
                    *(float2*)&C[(size_t)row * NC + col] = v;
                }
            }
    }
}

// ---------------------------------------------------------------------------
// Flash attention, bf16x3 mma, cp.async double-buffered K/V, 2 CTAs/SM.
// CTA = (b, h, 128 q rows), 8 warps, kv tiles of 64.
// ---------------------------------------------------------------------------
#define AT_Q 9216            // 128*72
#define AT_T 4608            // 64*72
#define AT_KV (2 * AT_Q)

__global__ __launch_bounds__(256, 2) void attn_mma2() {
    extern __shared__ __align__(16) __nv_bfloat16 smem[];
    const int tid = threadIdx.x, lane = tid & 31, w = tid >> 5;
    const int q0 = blockIdx.x * 128, h = blockIdx.y, b = blockIdx.z;
    const size_t hb = (size_t)(b * HH + h) * SS * DD;

    const uint32_t uS = (uint32_t)__cvta_generic_to_shared(smem);
    const uint32_t uQh = uS, uQl = uS + AT_Q * 2;

    const int lm_r = lane & 15, lm_c = (lane >> 4) * 8;
    const int bn_r = (lane & 7) + (lane >> 4) * 8;
    const int bn_c = ((lane >> 3) & 1) * 8;

    auto kv_base = [&](int buf, int t) -> uint32_t {
        return uS + (AT_KV + (buf * 4 + t) * AT_T) * 2;
    };

    auto load_kv = [&](int buf, int kv) {
        const __nv_bfloat16* s0 = g_kh + hb + (size_t)kv * DD;
        const __nv_bfloat16* s1 = g_kl + hb + (size_t)kv * DD;
        const __nv_bfloat16* s2 = g_vh + hb + (size_t)kv * DD;
        const __nv_bfloat16* s3 = g_vl + hb + (size_t)kv * DD;
#pragma unroll
        for (int i = 0; i < 2; i++) {
            int idx = tid + i * 256;               // 0..511
            int r = idx >> 3, c8 = (idx & 7) * 8;  // r 0..63, c8 0..56
            uint32_t so = (r * 72 + c8) * 2;
            int go = r * DD + c8;
            cp16(kv_base(buf, 0) + so, s0 + go);
            cp16(kv_base(buf, 1) + so, s1 + go);
            cp16(kv_base(buf, 2) + so, s2 + go);
            cp16(kv_base(buf, 3) + so, s3 + go);
        }
    };

    // group 0: Q + first KV tile
#pragma unroll
    for (int i = 0; i < 4; i++) {
        int idx = tid + i * 256;                   // 0..1023
        int r = idx >> 3, c8 = (idx & 7) * 8;      // r 0..127
        uint32_t so = (r * 72 + c8) * 2;
        size_t go = hb + (size_t)(q0 + r) * DD + c8;
        cp16(uQh + so, g_qh + go);
        cp16(uQl + so, g_ql + go);
    }
    load_kv(0, 0);
    cp_commit();

    float m1 = -1.0e30f, m2 = -1.0e30f, l1 = 0.0f, l2 = 0.0f;
    float oacc[8][4];
#pragma unroll
    for (int j = 0; j < 8; j++)
#pragma unroll
        for (int q = 0; q < 4; q++) oacc[j][q] = 0.0f;

#pragma unroll 1
    for (int ti = 0; ti < 32; ti++) {
        const int buf = ti & 1;
        if (ti + 1 < 32) load_kv(buf ^ 1, (ti + 1) * 64);
        cp_commit();
        if (ti + 1 < 32) cp_wait<1>(); else cp_wait<0>();
        __syncthreads();

        const uint32_t uKh = kv_base(buf, 0), uKl = kv_base(buf, 1);
        const uint32_t uVh = kv_base(buf, 2), uVl = kv_base(buf, 3);

        // S = Q @ K^T  (scale folded into Q)
        float sacc[8][4];
#pragma unroll
        for (int j = 0; j < 8; j++)
#pragma unroll
            for (int q = 0; q < 4; q++) sacc[j][q] = 0.0f;

#pragma unroll
        for (int kt = 0; kt < 4; kt++) {
            unsigned ah[4], al[4];
            uint32_t qoff = ((w * 16 + lm_r) * 72 + kt * 16 + lm_c) * 2;
            ldsm4(ah, uQh + qoff);
            ldsm4(al, uQl + qoff);
#pragma unroll
            for (int g = 0; g < 4; g++) {
                unsigned bh[4], bl[4];
                uint32_t koff = ((g * 16 + bn_r) * 72 + kt * 16 + bn_c) * 2;
                ldsm4(bh, uKh + koff);
                ldsm4(bl, uKl + koff);
                mma_bf16(sacc[2 * g],     ah, &bh[0]);
                mma_bf16(sacc[2 * g],     ah, &bl[0]);
                mma_bf16(sacc[2 * g],     al, &bh[0]);
                mma_bf16(sacc[2 * g + 1], ah, &bh[2]);
                mma_bf16(sacc[2 * g + 1], ah, &bl[2]);
                mma_bf16(sacc[2 * g + 1], al, &bh[2]);
            }
        }

        // Online softmax
        float mx1 = -1.0e30f, mx2 = -1.0e30f;
#pragma unroll
        for (int nt = 0; nt < 8; nt++) {
            mx1 = fmaxf(mx1, fmaxf(sacc[nt][0], sacc[nt][1]));
            mx2 = fmaxf(mx2, fmaxf(sacc[nt][2], sacc[nt][3]));
        }
#pragma unroll
        for (int off = 1; off <= 2; off <<= 1) {
            mx1 = fmaxf(mx1, __shfl_xor_sync(0xffffffffu, mx1, off));
            mx2 = fmaxf(mx2, __shfl_xor_sync(0xffffffffu, mx2, off));
        }
        float mn1 = fmaxf(m1, mx1), mn2 = fmaxf(m2, mx2);
        float fac1 = __expf(m1 - mn1), fac2 = __expf(m2 - mn2);
        float rs1 = 0.0f, rs2 = 0.0f;
#pragma unroll
        for (int nt = 0; nt < 8; nt++) {
            sacc[nt][0] = __expf(sacc[nt][0] - mn1);
            sacc[nt][1] = __expf(sacc[nt][1] - mn1);
            sacc[nt][2] = __expf(sacc[nt][2] - mn2);
            sacc[nt][3] = __expf(sacc[nt][3] - mn2);
            rs1 += sacc[nt][0] + sacc[nt][1];
            rs2 += sacc[nt][2] + sacc[nt][3];
        }
#pragma unroll
        for (int off = 1; off <= 2; off <<= 1) {
            rs1 += __shfl_xor_sync(0xffffffffu, rs1, off);
            rs2 += __shfl_xor_sync(0xffffffffu, rs2, off);
        }
        l1 = l1 * fac1 + rs1;
        l2 = l2 * fac2 + rs2;
        m1 = mn1;
        m2 = mn2;
#pragma unroll
        for (int nt = 0; nt < 8; nt++) {
            oacc[nt][0] *= fac1;
            oacc[nt][1] *= fac1;
            oacc[nt][2] *= fac2;
            oacc[nt][3] *= fac2;
        }

        // P fragments (hi/lo) straight from sacc registers
        unsigned ph[4][4], pl[4][4];
#pragma unroll
        for (int kt = 0; kt < 4; kt++) {
            split_pair(sacc[2 * kt][0],     sacc[2 * kt][1],     ph[kt][0], pl[kt][0]);
            split_pair(sacc[2 * kt][2],     sacc[2 * kt][3],     ph[kt][1], pl[kt][1]);
            split_pair(sacc[2 * kt + 1][0], sacc[2 * kt + 1][1], ph[kt][2], pl[kt][2]);
            split_pair(sacc[2 * kt + 1][2], sacc[2 * kt + 1][3], ph[kt][3], pl[kt][3]);
        }

        // O += P @ V
#pragma unroll
        for (int kt = 0; kt < 4; kt++) {
#pragma unroll
            for (int dg = 0; dg < 4; dg++) {
                unsigned vh[4], vl[4];
                uint32_t voff = ((kt * 16 + lm_r) * 72 + dg * 16 + lm_c) * 2;
                ldsm4t(vh, uVh + voff);
                ldsm4t(vl, uVl + voff);
                mma_bf16(oacc[2 * dg],     ph[kt], &vh[0]);
                mma_bf16(oacc[2 * dg],     ph[kt], &vl[0]);
                mma_bf16(oacc[2 * dg],     pl[kt], &vh[0]);
                mma_bf16(oacc[2 * dg + 1], ph[kt], &vh[2]);
                mma_bf16(oacc[2 * dg + 1], ph[kt], &vl[2]);
                mma_bf16(oacc[2 * dg + 1], pl[kt], &vh[2]);
            }
        }
        __syncthreads();
    }

    // normalize + store O hi/lo
    float inv1 = 1.0f / l1, inv2 = 1.0f / l2;
    int r1 = q0 + w * 16 + (lane >> 2);
#pragma unroll
    for (int nt = 0; nt < 8; nt++) {
        int d = nt * 8 + (lane & 3) * 2;
        unsigned hi, lo;
        split_pair(oacc[nt][0] * inv1, oacc[nt][1] * inv1, hi, lo);
        size_t off = ((size_t)(b * SS + r1)) * EE + h * DD + d;
        *(unsigned*)&g_oh[off] = hi;
        *(unsigned*)&g_ol[off] = lo;
        split_pair(oacc[nt][2] * inv2, oacc[nt][3] * inv2, hi, lo);
        off = ((size_t)(b * SS + r1 + 8)) * EE + h * DD + d;
        *(unsigned*)&g_oh[off] = hi;
        *(unsigned*)&g_ol[off] = lo;
    }
}

// ---------------------------------------------------------------------------
extern "C" void kernel_launch(void* const* d_in, const int* in_sizes, int n_in,
                              void* d_out, int out_size) {
    const float* x = (const float*)d_in[0];      // (B, S, E)
    const float* w_qkv = (const float*)d_in[1];  // (E, 3E)
    const float* w_out = (const float*)d_in[2];  // (E, E)
    float* out = (float*)d_out;                  // (B, S, E)

    __nv_bfloat16 *p_xh, *p_xl, *p_wqh, *p_wql, *p_woh, *p_wol;
    __nv_bfloat16 *p_oh, *p_ol;
    cudaGetSymbolAddress((void**)&p_xh, g_xh);
    cudaGetSymbolAddress((void**)&p_xl, g_xl);
    cudaGetSymbolAddress((void**)&p_wqh, g_wqh);
    cudaGetSymbolAddress((void**)&p_wql, g_wql);
    cudaGetSymbolAddress((void**)&p_woh, g_woh);
    cudaGetSymbolAddress((void**)&p_wol, g_wol);
    cudaGetSymbolAddress((void**)&p_oh, g_oh);
    cudaGetSymbolAddress((void**)&p_ol, g_ol);

    // 0) split inputs once
    split_kernel<<<(BB*SS*EE/4 + 255) / 256, 256>>>(x, p_xh, p_xl, BB*SS*EE/4);
    split_kernel<<<(EE*NQKV/4 + 255) / 256, 256>>>(w_qkv, p_wqh, p_wql, EE*NQKV/4);
    split_kernel<<<(EE*EE/4 + 255) / 256, 256>>>(w_out, p_woh, p_wol, EE*EE/4);

    const int gemm_smem = (4 * GA_STRIDE + 4 * GB_STRIDE) * (int)sizeof(__nv_bfloat16);

    // 1) QKV projection, scatter Q/K/V hi/lo (Q pre-scaled)
    cudaFuncSetAttribute(mma_gemm2<NQKV, true>,
                         cudaFuncAttributeMaxDynamicSharedMemorySize, gemm_smem);
    mma_gemm2<NQKV, true><<<dim3(NQKV / 128, (BB * SS) / 128), 256, gemm_smem>>>(
        p_xh, p_xl, p_wqh, p_wql, nullptr);

    // 2) Flash attention
    const int attn_smem = (AT_KV + 8 * AT_T) * (int)sizeof(__nv_bfloat16);
    cudaFuncSetAttribute(attn_mma2, cudaFuncAttributeMaxDynamicSharedMemorySize,
                         attn_smem);
    attn_mma2<<<dim3(SS / 128, HH, BB), 256, attn_smem>>>();

    // 3) Output projection
    cudaFuncSetAttribute(mma_gemm2<EE, false>,
                         cudaFuncAttributeMaxDynamicSharedMemorySize, gemm_smem);
    mma_gemm2<EE, false><<<dim3(EE / 128, (BB * SS) / 128), 256, gemm_smem>>>(
        p_oh, p_ol, p_woh, p_wol, out);
}